// round 16
// baseline (speedup 1.0000x reference)
#include <cuda_runtime.h>
#include <stdint.h>

// L2-only gather (no L1 allocation: random 4B reads have ~0% L1 hit rate,
// and the wasted 32B sector fills were saturating L1tex).
__device__ __forceinline__ int ldg_cg(const int* p) {
    int v;
    asm volatile("ld.global.cg.b32 %0, [%1];" : "=r"(v) : "l"(p));
    return v;
}

// One fused kernel used for both passes.
// Block ranges: [0,zero_blocks) zero output | [.., +pf_blocks) prefetch table
// slice | rest: process 8 arcs/thread whose pins fall in [lo, hi).
__global__ void fused_pass(
    const float*  __restrict__ beta,
    const float4* __restrict__ w4,        // [num_tnets/4]
    const int4*   __restrict__ pins4,     // [num_tnets/2]
    const int*    __restrict__ pin2node,
    float* __restrict__ out,
    int num_octs,                         // num_tnets/8
    int lo, int hi,
    int zero_blocks, int pf_blocks,
    long pf_start_byte, long pf_bytes, int n_out)
{
    unsigned b = blockIdx.x;
    if (b < (unsigned)zero_blocks) {
        int i = b * blockDim.x + threadIdx.x;
        int n4 = n_out >> 2;
        if (i < n4) reinterpret_cast<float4*>(out)[i] = make_float4(0.f,0.f,0.f,0.f);
        return;
    }
    b -= zero_blocks;
    if (b < (unsigned)pf_blocks) {
        long line = (long)b * blockDim.x + threadIdx.x;
        if (line * 128 < pf_bytes) {
            const char* p = (const char*)pin2node + pf_start_byte + line * 128;
            asm volatile("prefetch.global.L2 [%0];" :: "l"(p));
        }
        return;
    }
    b -= pf_blocks;
    int i = b * blockDim.x + threadIdx.x;
    if (i >= num_octs) return;

    float bt = __ldg(beta);
    // 8 arcs = 8 weights (2x float4) + 16 pins (4x int4), streaming loads.
    float4 wA = __ldcs(&w4[2*i]);
    float4 wB = __ldcs(&w4[2*i + 1]);
    int4 p0 = __ldcs(&pins4[4*i]);
    int4 p1 = __ldcs(&pins4[4*i + 1]);
    int4 p2 = __ldcs(&pins4[4*i + 2]);
    int4 p3 = __ldcs(&pins4[4*i + 3]);

    float w0 = wA.x * bt, w1 = wA.y * bt, w2 = wA.z * bt, w3 = wA.w * bt;
    float w4v = wB.x * bt, w5 = wB.y * bt, w6 = wB.z * bt, w7 = wB.w * bt;

    #define PROC(pin, wb)                          \
        if ((pin) >= lo && (pin) < hi) {           \
            int n = ldg_cg(&pin2node[(pin)]);      \
            atomicAdd(out + n, (wb));              \
        }
    PROC(p0.x, w0) PROC(p0.y, w0) PROC(p0.z, w1) PROC(p0.w, w1)
    PROC(p1.x, w2) PROC(p1.y, w2) PROC(p1.z, w3) PROC(p1.w, w3)
    PROC(p2.x, w4v) PROC(p2.y, w4v) PROC(p2.z, w5) PROC(p2.w, w5)
    PROC(p3.x, w6) PROC(p3.y, w6) PROC(p3.z, w7) PROC(p3.w, w7)
    #undef PROC
}

extern "C" void kernel_launch(void* const* d_in, const int* in_sizes, int n_in,
                              void* d_out, int out_size)
{
    const float* beta     = (const float*)d_in[0];
    const float* tnet_w   = (const float*)d_in[1];
    const int*   flat_t2p = (const int*)d_in[2];
    const int*   pin2node = (const int*)d_in[3];
    float*       out      = (float*)d_out;

    int  num_tnets = in_sizes[1];              // 8388608
    int  num_pins  = in_sizes[3];              // 20971520
    int  num_nodes = out_size;                 // 1048576
    int  num_octs  = num_tnets >> 3;           // 1048576
    int  mid       = num_pins >> 1;

    const int threads = 256;
    int arc_blocks  = (num_octs + threads - 1) / threads;         // 4096
    int zero_blocks = ((num_nodes >> 2) + threads - 1) / threads; // 1024

    long half_bytes = (long)mid * 4;                              // 40 MB
    int  pf_blocks  = (int)((half_bytes / 128 + threads - 1) / threads);

    // Pass 0: zero output, prefetch table[0, mid), process pins < mid
    fused_pass<<<zero_blocks + pf_blocks + arc_blocks, threads>>>(
        beta, (const float4*)tnet_w, (const int4*)flat_t2p, pin2node, out,
        num_octs, 0, mid,
        zero_blocks, pf_blocks, 0, half_bytes, num_nodes);

    // Pass 1: prefetch table[mid, num_pins), process pins >= mid
    long rest_bytes = (long)(num_pins - mid) * 4;
    int  pf_blocks1 = (int)((rest_bytes / 128 + threads - 1) / threads);
    fused_pass<<<pf_blocks1 + arc_blocks, threads>>>(
        beta, (const float4*)tnet_w, (const int4*)flat_t2p, pin2node, out,
        num_octs, mid, num_pins,
        0, pf_blocks1, half_bytes, rest_bytes, num_nodes);
}

// round 17
// speedup vs baseline: 1.1324x; 1.1324x over previous
#include <cuda_runtime.h>
#include <stdint.h>

// L2-only gather: random 4B reads have ~0% L1 hit rate; skip L1 allocation
// to relieve L1tex sector-fill pressure.
__device__ __forceinline__ int ldg_cg(const int* p) {
    int v;
    asm volatile("ld.global.cg.b32 %0, [%1];" : "=r"(v) : "l"(p));
    return v;
}

// One fused kernel used for both passes.
// Block ranges: [0,zero_blocks) zero output | [.., +pf_blocks) prefetch table
// slice | rest: process 4 arcs/thread whose pins fall in [lo, hi).
__global__ void fused_pass(
    const float*  __restrict__ beta,
    const float4* __restrict__ w4,        // [num_tnets/4]
    const int4*   __restrict__ pins4,     // [num_tnets/2] (2 int4 per quad)
    const int*    __restrict__ pin2node,
    float* __restrict__ out,
    int num_quads, int lo, int hi,
    int zero_blocks, int pf_blocks,
    long pf_start_byte, long pf_bytes, int n_out)
{
    unsigned b = blockIdx.x;
    if (b < (unsigned)zero_blocks) {
        int i = b * blockDim.x + threadIdx.x;
        int n4 = n_out >> 2;
        if (i < n4) reinterpret_cast<float4*>(out)[i] = make_float4(0.f,0.f,0.f,0.f);
        return;
    }
    b -= zero_blocks;
    if (b < (unsigned)pf_blocks) {
        long line = (long)b * blockDim.x + threadIdx.x;
        if (line * 128 < pf_bytes) {
            const char* p = (const char*)pin2node + pf_start_byte + line * 128;
            asm volatile("prefetch.global.L2 [%0];" :: "l"(p));
        }
        return;
    }
    b -= pf_blocks;
    int i = b * blockDim.x + threadIdx.x;
    if (i >= num_quads) return;

    float bt = __ldg(beta);
    float4 w  = __ldcs(&w4[i]);
    int4   pa = __ldcs(&pins4[2*i]);
    int4   pb = __ldcs(&pins4[2*i + 1]);

    float wb0 = w.x * bt, wb1 = w.y * bt, wb2 = w.z * bt, wb3 = w.w * bt;

    #define PROC(pin, wb)                          \
        if ((pin) >= lo && (pin) < hi) {           \
            int n = ldg_cg(&pin2node[(pin)]);      \
            atomicAdd(out + n, (wb));              \
        }
    PROC(pa.x, wb0) PROC(pa.y, wb0)
    PROC(pa.z, wb1) PROC(pa.w, wb1)
    PROC(pb.x, wb2) PROC(pb.y, wb2)
    PROC(pb.z, wb3) PROC(pb.w, wb3)
    #undef PROC
}

extern "C" void kernel_launch(void* const* d_in, const int* in_sizes, int n_in,
                              void* d_out, int out_size)
{
    const float* beta     = (const float*)d_in[0];
    const float* tnet_w   = (const float*)d_in[1];
    const int*   flat_t2p = (const int*)d_in[2];
    const int*   pin2node = (const int*)d_in[3];
    float*       out      = (float*)d_out;

    int  num_tnets = in_sizes[1];              // 8388608
    int  num_pins  = in_sizes[3];              // 20971520
    int  num_nodes = out_size;                 // 1048576
    int  num_quads = num_tnets >> 2;           // 2097152
    int  mid       = num_pins >> 1;

    const int threads = 256;
    int arc_blocks  = (num_quads + threads - 1) / threads;        // 8192
    int zero_blocks = ((num_nodes >> 2) + threads - 1) / threads; // 1024

    long half_bytes = (long)mid * 4;                              // 40 MB
    int  pf_blocks  = (int)((half_bytes / 128 + threads - 1) / threads);

    // Pass 0: zero output, prefetch table[0, mid), process pins < mid
    fused_pass<<<zero_blocks + pf_blocks + arc_blocks, threads>>>(
        beta, (const float4*)tnet_w, (const int4*)flat_t2p, pin2node, out,
        num_quads, 0, mid,
        zero_blocks, pf_blocks, 0, half_bytes, num_nodes);

    // Pass 1: prefetch table[mid, num_pins), process pins >= mid
    long rest_bytes = (long)(num_pins - mid) * 4;
    int  pf_blocks1 = (int)((rest_bytes / 128 + threads - 1) / threads);
    fused_pass<<<pf_blocks1 + arc_blocks, threads>>>(
        beta, (const float4*)tnet_w, (const int4*)flat_t2p, pin2node, out,
        num_quads, mid, num_pins,
        0, pf_blocks1, half_bytes, rest_bytes, num_nodes);
}